// round 7
// baseline (speedup 1.0000x reference)
#include <cuda_runtime.h>

// LSTM: B=4096, T=512, I=10, H=32, O=1. Gate order i,f,g,o.
// R7: R4 logic (NB=2 batches per single-warp block, R2's k-inner interleaved
// schedule, f32x2 packed fma with even/odd-j halves in u64 halves), but the
// o-gate recurrent weights live in SMEM (saves 32 regs) so regs <= 146 and
// ALL 2048 blocks fit in ONE wave at 14 warps/SM (vs R4's 12 -> two waves).

#define B_TOT 4096
#define T_LEN 512
#define I_DIM 10
#define H_DIM 32
#define NB 2
#define NPX 5

typedef unsigned long long u64;

__device__ __forceinline__ u64 fma2(u64 a, u64 b, u64 c) {
    u64 d;
    asm("fma.rn.f32x2 %0, %1, %2, %3;" : "=l"(d) : "l"(a), "l"(b), "l"(c));
    return d;
}
__device__ __forceinline__ u64 pack2(float lo, float hi) {
    u64 d;
    asm("mov.b64 %0, {%1, %2};" : "=l"(d) : "f"(lo), "f"(hi));
    return d;
}
__device__ __forceinline__ void unpack2(u64 v, float& lo, float& hi) {
    asm("mov.b64 {%0, %1}, %2;" : "=f"(lo), "=f"(hi) : "l"(v));
}
__device__ __forceinline__ float ex2f(float x) {
    float y; asm("ex2.approx.f32 %0, %1;" : "=f"(y) : "f"(x)); return y;
}
__device__ __forceinline__ float rcpf(float x) {
    float y; asm("rcp.approx.f32 %0, %1;" : "=f"(y) : "f"(x)); return y;
}
__device__ __forceinline__ float sigf(float x) {
    return rcpf(1.0f + ex2f(-1.4426950408889634f * x));
}
__device__ __forceinline__ float tanh_f(float x) {
    return fmaf(2.0f, rcpf(1.0f + ex2f(-2.8853900817779268f * x)), -1.0f);
}

__global__ __launch_bounds__(32, 14) void lstm_r7_kernel(
    const float* __restrict__ x,    // [B, T, I]
    const float* __restrict__ Wih,  // [4H, I]
    const float* __restrict__ Whh,  // [4H, H]
    const float* __restrict__ bih,  // [4H]
    const float* __restrict__ bhh,  // [4H]
    const float* __restrict__ Wd,   // [1, H]
    const float* __restrict__ bd,   // [1]
    float* __restrict__ out)        // [B, 1]
{
    // o-gate recurrent weights: sWo[q][lane] = (pair j=4q..4q+1, pair j=4q+2..4q+3)
    __shared__ ulonglong2 sWo[8][32];        // 4 KB
    __shared__ ulonglong2 sWx_if[NPX][32];   // 2.5 KB
    __shared__ ulonglong2 sWx_go[NPX][32];   // 2.5 KB
    __shared__ __align__(16) float sH[NB][H_DIM];
    __shared__ __align__(16) float sX[NB][12];

    const int lane = threadIdx.x;
    const int b0 = blockIdx.x * NB;

    // ---- i, f, g recurrent weights into registers (paired over j) ----
    u64 whi[16], whf[16], whg[16];
#pragma unroll
    for (int p = 0; p < 16; p++) {
        whi[p] = *(const u64*)&Whh[(0 * 32 + lane) * H_DIM + 2 * p];
        whf[p] = *(const u64*)&Whh[(1 * 32 + lane) * H_DIM + 2 * p];
        whg[p] = *(const u64*)&Whh[(2 * 32 + lane) * H_DIM + 2 * p];
    }
    // o-gate recurrent weights into smem.
#pragma unroll
    for (int q = 0; q < 8; q++) {
        ulonglong2 v;
        v.x = *(const u64*)&Whh[(3 * 32 + lane) * H_DIM + 4 * q];
        v.y = *(const u64*)&Whh[(3 * 32 + lane) * H_DIM + 4 * q + 2];
        sWo[q][lane] = v;
    }
    // x-weights into smem, packed per gate-pair.
#pragma unroll
    for (int p = 0; p < NPX; p++) {
        ulonglong2 v;
        v.x = pack2(Wih[(0 * 32 + lane) * I_DIM + 2 * p], Wih[(0 * 32 + lane) * I_DIM + 2 * p + 1]);
        v.y = pack2(Wih[(1 * 32 + lane) * I_DIM + 2 * p], Wih[(1 * 32 + lane) * I_DIM + 2 * p + 1]);
        sWx_if[p][lane] = v;
        v.x = pack2(Wih[(2 * 32 + lane) * I_DIM + 2 * p], Wih[(2 * 32 + lane) * I_DIM + 2 * p + 1]);
        v.y = pack2(Wih[(3 * 32 + lane) * I_DIM + 2 * p], Wih[(3 * 32 + lane) * I_DIM + 2 * p + 1]);
        sWx_go[p][lane] = v;
    }
    const u64 bp_i = pack2(bih[0 * 32 + lane] + bhh[0 * 32 + lane], 0.0f);
    const u64 bp_f = pack2(bih[1 * 32 + lane] + bhh[1 * 32 + lane], 0.0f);
    const u64 bp_g = pack2(bih[2 * 32 + lane] + bhh[2 * 32 + lane], 0.0f);
    const u64 bp_o = pack2(bih[3 * 32 + lane] + bhh[3 * 32 + lane], 0.0f);
    __syncwarp();

    float h[NB], c[NB], xv[NB];
#pragma unroll
    for (int k = 0; k < NB; k++) { h[k] = 0.0f; c[k] = 0.0f; xv[k] = 0.0f; }

    const float* xp0 = x + ((b0 + 0) * T_LEN) * I_DIM + lane;
    const float* xp1 = x + ((b0 + 1) * T_LEN) * I_DIM + lane;
    if (lane < I_DIM) { xv[0] = *xp0; xv[1] = *xp1; }

    for (int t = 0; t < T_LEN; t++) {
        // Publish compact h and x.
        sH[0][lane] = h[0];
        sH[1][lane] = h[1];
        if (lane < I_DIM) {
            sX[0][lane] = xv[0];
            sX[1][lane] = xv[1];
        }
        __syncwarp();

        // Prefetch next timestep's x (overlaps gate compute below).
        if (t + 1 < T_LEN) {
            xp0 += I_DIM; xp1 += I_DIM;
            if (lane < I_DIM) { xv[0] = *xp0; xv[1] = *xp1; }
        }

        // Accumulators: lo half = even-j sum, hi half = odd-j sum (bias in lo).
        u64 ai[NB], af[NB], ag[NB], ao[NB];
#pragma unroll
        for (int k = 0; k < NB; k++) { ai[k] = bp_i; af[k] = bp_f; ag[k] = bp_g; ao[k] = bp_o; }

        // Recurrent part: q-outer, both batches inner (16 indep fma chains).
#pragma unroll
        for (int q = 0; q < 8; q++) {
            const ulonglong2 wo = sWo[q][lane];
            const ulonglong2 hp0 = *(const ulonglong2*)&sH[0][4 * q];
            const ulonglong2 hp1 = *(const ulonglong2*)&sH[1][4 * q];
            ai[0] = fma2(whi[2 * q],     hp0.x, ai[0]);
            ai[1] = fma2(whi[2 * q],     hp1.x, ai[1]);
            af[0] = fma2(whf[2 * q],     hp0.x, af[0]);
            af[1] = fma2(whf[2 * q],     hp1.x, af[1]);
            ag[0] = fma2(whg[2 * q],     hp0.x, ag[0]);
            ag[1] = fma2(whg[2 * q],     hp1.x, ag[1]);
            ao[0] = fma2(wo.x,           hp0.x, ao[0]);
            ao[1] = fma2(wo.x,           hp1.x, ao[1]);
            ai[0] = fma2(whi[2 * q + 1], hp0.y, ai[0]);
            ai[1] = fma2(whi[2 * q + 1], hp1.y, ai[1]);
            af[0] = fma2(whf[2 * q + 1], hp0.y, af[0]);
            af[1] = fma2(whf[2 * q + 1], hp1.y, af[1]);
            ag[0] = fma2(whg[2 * q + 1], hp0.y, ag[0]);
            ag[1] = fma2(whg[2 * q + 1], hp1.y, ag[1]);
            ao[0] = fma2(wo.y,           hp0.y, ao[0]);
            ao[1] = fma2(wo.y,           hp1.y, ao[1]);
        }
        // Input part.
#pragma unroll
        for (int p = 0; p < NPX; p++) {
            const ulonglong2 wif = sWx_if[p][lane];
            const ulonglong2 wgo = sWx_go[p][lane];
#pragma unroll
            for (int k = 0; k < NB; k++) {
                const u64 xq = *(const u64*)&sX[k][2 * p];
                ai[k] = fma2(wif.x, xq, ai[k]);
                af[k] = fma2(wif.y, xq, af[k]);
                ag[k] = fma2(wgo.x, xq, ag[k]);
                ao[k] = fma2(wgo.y, xq, ao[k]);
            }
        }

        // Activations + state update.
#pragma unroll
        for (int k = 0; k < NB; k++) {
            float lo, hi;
            unpack2(ai[k], lo, hi); const float gi = sigf(lo + hi);
            unpack2(af[k], lo, hi); const float gf = sigf(lo + hi);
            unpack2(ag[k], lo, hi); const float gg = tanh_f(lo + hi);
            unpack2(ao[k], lo, hi); const float go = sigf(lo + hi);
            c[k] = fmaf(gf, c[k], gi * gg);
            h[k] = go * tanh_f(c[k]);
        }
        __syncwarp();
    }

    // Final dense: out[b] = sum_l h[b][l] * Wd[l] + bd
    const float wd = Wd[lane];
    const float bdv = bd[0];
#pragma unroll
    for (int k = 0; k < NB; k++) {
        float p = h[k] * wd;
#pragma unroll
        for (int off = 16; off; off >>= 1)
            p += __shfl_xor_sync(0xffffffffu, p, off);
        if (lane == 0) out[b0 + k] = p + bdv;
    }
}

extern "C" void kernel_launch(void* const* d_in, const int* in_sizes, int n_in,
                              void* d_out, int out_size) {
    const float* x   = (const float*)d_in[0];
    const float* Wih = (const float*)d_in[1];
    const float* Whh = (const float*)d_in[2];
    const float* bih = (const float*)d_in[3];
    const float* bhh = (const float*)d_in[4];
    const float* Wd  = (const float*)d_in[5];
    const float* bd  = (const float*)d_in[6];
    (void)in_sizes; (void)n_in; (void)out_size;

    lstm_r7_kernel<<<B_TOT / NB, 32>>>(x, Wih, Whh, bih, bhh, Wd, bd,
                                       (float*)d_out);
}